// round 13
// baseline (speedup 1.0000x reference)
#include <cuda_runtime.h>
#include <cuda_bf16.h>
#include <cuda_fp16.h>
#include <mma.h>
#include <cstdint>

using namespace nvcuda;

#define MAXN 50048
#define HID 128
#define MAXG 2048
#define MAXDEG 128

// Scratch (device globals; allocation is forbidden)
__device__ __half g_xh [(size_t)MAXN * HID];
__device__ __half g_hh [(size_t)MAXN * HID];
__device__ float  g_h2 [(size_t)MAXN * HID];
__device__ int    g_cur[MAXN];
__device__ int    g_esrc[(size_t)MAXN * MAXDEG];
__device__ __half g_Wh[4][HID * HID];
__device__ __half g_Wl[4][HID * HID];

// ---------------------------------------------------------------------------
// cp.async helpers
// ---------------------------------------------------------------------------
__device__ __forceinline__ void cp_async16(uint32_t dst, const void* src)
{
    asm volatile("cp.async.ca.shared.global [%0], [%1], 16;\n"
                 :: "r"(dst), "l"(src));
}
__device__ __forceinline__ void cp_commit()
{
    asm volatile("cp.async.commit_group;\n" ::: "memory");
}

// ---------------------------------------------------------------------------
// Fused prep kernel: edge fill + x f32->f16 + weight pre-split
// ---------------------------------------------------------------------------
__global__ __launch_bounds__(256) void prep_kernel(
    const int* __restrict__ src, const int* __restrict__ dst,
    int* __restrict__ cur, int* __restrict__ esrc, int E, int fill_blocks,
    const float* __restrict__ x, __half* __restrict__ xh, int n8, int f2h_blocks,
    const float* __restrict__ W1a, const float* __restrict__ W1b,
    const float* __restrict__ W2a, const float* __restrict__ W2b,
    __half* __restrict__ Wh, __half* __restrict__ Wl)
{
    int b = blockIdx.x;
    if (b < fill_blocks) {
        int e = b * 256 + threadIdx.x;
        if (e < E) {
            int d = dst[e];
            int pos = atomicAdd(&cur[d], 1);
            if (pos < MAXDEG) esrc[(size_t)d * MAXDEG + pos] = src[e];
        }
    } else if (b < fill_blocks + f2h_blocks) {
        int i = (b - fill_blocks) * 256 + threadIdx.x;
        if (i < n8) {
            float4 a = *reinterpret_cast<const float4*>(x + (size_t)i * 8);
            float4 c = *reinterpret_cast<const float4*>(x + (size_t)i * 8 + 4);
            uint4 u;
            *reinterpret_cast<__half2*>(&u.x) = __floats2half2_rn(a.x, a.y);
            *reinterpret_cast<__half2*>(&u.y) = __floats2half2_rn(a.z, a.w);
            *reinterpret_cast<__half2*>(&u.z) = __floats2half2_rn(c.x, c.y);
            *reinterpret_cast<__half2*>(&u.w) = __floats2half2_rn(c.z, c.w);
            *reinterpret_cast<uint4*>(xh + (size_t)i * 8) = u;
        }
    } else {
        int i = (b - fill_blocks - f2h_blocks) * 256 + threadIdx.x;
        if (i < 4 * HID * HID) {
            int plane = i >> 14, idx = i & 16383;
            const float* s = (plane == 0) ? W1a : (plane == 1) ? W1b
                           : (plane == 2) ? W2a : W2b;
            float v = s[idx];
            __half h = __float2half(v);
            __half l = __float2half(v - __half2float(h));
            Wh[i] = h;
            Wl[i] = l;
        }
    }
}

// ---------------------------------------------------------------------------
// Fused GIN layer: gather (into smem) + GEMM1 + GEMM2.
//   Phase 0: each block gathers its 128 nodes' agg = x[i] + sum_j x[j]
//            (fp32 accum from fp16) straight into Af[128][136] as fp16.
//   Phase 1: T = relu(Af @ Wa + ba) written in place over Af.
//   Phase 2: out = relu(Af @ Wb + bb) -> fp16 (Ch) or fp32 (Cf).
// W planes fp16 hi+lo (2-term split), cp.async double-buffered.
// Dynamic smem 69632 B: Af[0,34816) | Wbuf0[34816,52224) | Wbuf1[52224,69632)
// NO min-blocks launch bound: regs ~128, 2 CTA/SM (the R12 reg-cap spill bug).
// ---------------------------------------------------------------------------
#define AF_OFF   0
#define WBUF0    34816
#define WBUF1    52224
#define FUSED_SMEM 69632

__device__ __forceinline__ void acc_row(const uint4& u, float4& a, float4& b)
{
    float2 f;
    f = __half22float2(*reinterpret_cast<const __half2*>(&u.x)); a.x += f.x; a.y += f.y;
    f = __half22float2(*reinterpret_cast<const __half2*>(&u.y)); a.z += f.x; a.w += f.y;
    f = __half22float2(*reinterpret_cast<const __half2*>(&u.z)); b.x += f.x; b.y += f.y;
    f = __half22float2(*reinterpret_cast<const __half2*>(&u.w)); b.z += f.x; b.w += f.y;
}

__global__ __launch_bounds__(256) void fused_layer_kernel(
    const __half* __restrict__ xh, const int* __restrict__ esrc,
    const int* __restrict__ deg_arr,
    const __half* __restrict__ Wah, const __half* __restrict__ Wal,
    const float* __restrict__ ba,
    const __half* __restrict__ Wbh, const __half* __restrict__ Wbl,
    const float* __restrict__ bb,
    float* __restrict__ Cf, __half* __restrict__ Ch, int Nn)
{
    extern __shared__ char smem_raw[];
    const uint32_t smem_u32 = (uint32_t)__cvta_generic_to_shared(smem_raw);
    __half* Af = (__half*)(smem_raw + AF_OFF);        // [128][136]

    const int tid  = threadIdx.x;
    const int warp = tid >> 5;
    const int lane = tid & 31;
    const int wm = warp & 1;    // 64-row half
    const int wn = warp >> 1;   // 32-col quarter
    const int row0 = blockIdx.x * 128;

    auto prefetch_W = [&](int buf, int kc, const __half* Wh_, const __half* Wl_) {
        uint32_t sBh = smem_u32 + (buf ? WBUF1 : WBUF0);
        uint32_t sBl = sBh + 8704;
        #pragma unroll
        for (int i = tid; i < 512; i += 256) {
            int r = i >> 4, c8 = (i & 15) * 8;
            size_t goff = (size_t)(kc + r) * HID + c8;
            cp_async16(sBh + (r * 136 + c8) * 2, Wh_ + goff);
            cp_async16(sBl + (r * 136 + c8) * 2, Wl_ + goff);
        }
        cp_commit();
    };

    // Kick off GEMM1's first W tile; lands while we gather.
    prefetch_W(0, 0, Wah, Wal);

    // ---- Phase 0: gather agg for this block's 128 nodes into Af ----
    {
        const int hw  = tid >> 4;       // half-warp id 0..15
        const int l16 = tid & 15;
        const int col = l16 * 8;
        #pragma unroll
        for (int pass = 0; pass < 8; pass++) {
            int r = pass * 16 + hw;
            int gr = row0 + r;
            float4 accA = make_float4(0.f, 0.f, 0.f, 0.f);
            float4 accB = make_float4(0.f, 0.f, 0.f, 0.f);
            if (gr < Nn) {
                uint4 u = *reinterpret_cast<const uint4*>(xh + (size_t)gr * HID + col);
                acc_row(u, accA, accB);
                int deg = min(deg_arr[gr], MAXDEG);
                const int* rowp = esrc + (size_t)gr * MAXDEG;
                int e = 0;
                for (; e + 4 <= deg; e += 4) {
                    int4 s = *reinterpret_cast<const int4*>(rowp + e);
                    uint4 u0 = *reinterpret_cast<const uint4*>(xh + (size_t)s.x * HID + col);
                    uint4 u1 = *reinterpret_cast<const uint4*>(xh + (size_t)s.y * HID + col);
                    uint4 u2 = *reinterpret_cast<const uint4*>(xh + (size_t)s.z * HID + col);
                    uint4 u3 = *reinterpret_cast<const uint4*>(xh + (size_t)s.w * HID + col);
                    acc_row(u0, accA, accB);
                    acc_row(u1, accA, accB);
                    acc_row(u2, accA, accB);
                    acc_row(u3, accA, accB);
                }
                for (; e < deg; e++) {
                    int s = __ldg(rowp + e);
                    uint4 u2 = *reinterpret_cast<const uint4*>(xh + (size_t)s * HID + col);
                    acc_row(u2, accA, accB);
                }
            }
            uint4 o;
            *reinterpret_cast<__half2*>(&o.x) = __floats2half2_rn(accA.x, accA.y);
            *reinterpret_cast<__half2*>(&o.y) = __floats2half2_rn(accA.z, accA.w);
            *reinterpret_cast<__half2*>(&o.z) = __floats2half2_rn(accB.x, accB.y);
            *reinterpret_cast<__half2*>(&o.w) = __floats2half2_rn(accB.z, accB.w);
            *reinterpret_cast<uint4*>(Af + r * 136 + col) = o;
        }
    }

    wmma::fragment<wmma::accumulator, 16, 16, 16, float> acc[4][2];
    #pragma unroll
    for (int i = 0; i < 4; i++)
        #pragma unroll
        for (int j = 0; j < 2; j++) wmma::fill_fragment(acc[i][j], 0.0f);

    // ================= GEMM 1: T = relu(Af @ Wa + ba) =================
    #pragma unroll
    for (int k = 0; k < 4; k++) {
        asm volatile("cp.async.wait_group 0;\n" ::: "memory");
        __syncthreads();
        if (k < 3) prefetch_W((k + 1) & 1, (k + 1) * 32, Wah, Wal);

        __half* BhB = (__half*)(smem_raw + ((k & 1) ? WBUF1 : WBUF0));
        __half* BlB = BhB + 4352;

        #pragma unroll
        for (int kk = 0; kk < 32; kk += 16) {
            wmma::fragment<wmma::matrix_a, 16, 16, 16, __half, wmma::row_major> a[4];
            wmma::fragment<wmma::matrix_b, 16, 16, 16, __half, wmma::row_major> bh[2], bl[2];
            #pragma unroll
            for (int i = 0; i < 4; i++)
                wmma::load_matrix_sync(a[i], Af + (wm * 64 + i * 16) * 136 + k * 32 + kk, 136);
            #pragma unroll
            for (int j = 0; j < 2; j++) {
                wmma::load_matrix_sync(bh[j], BhB + kk * 136 + wn * 32 + j * 16, 136);
                wmma::load_matrix_sync(bl[j], BlB + kk * 136 + wn * 32 + j * 16, 136);
            }
            #pragma unroll
            for (int i = 0; i < 4; i++)
                #pragma unroll
                for (int j = 0; j < 2; j++) {
                    wmma::mma_sync(acc[i][j], a[i], bl[j], acc[i][j]);
                    wmma::mma_sync(acc[i][j], a[i], bh[j], acc[i][j]);
                }
        }
        __syncthreads();
    }

    // Prefetch GEMM2's first W tile into buf0 (overlaps epilogue 1)
    prefetch_W(0, 0, Wbh, Wbl);

    // epilogue 1: bias + relu -> T written IN PLACE over Af.
    // stage aliases Wbuf1 (last G1 tile used buf1; reads fenced by sync above)
    {
        float* stage = (float*)(smem_raw + WBUF1) + warp * 320;
        #pragma unroll
        for (int i = 0; i < 4; i++) {
            #pragma unroll
            for (int j = 0; j < 2; j++) {
                wmma::store_matrix_sync(stage, acc[i][j], 20, wmma::mem_row_major);
                __syncwarp();
                #pragma unroll
                for (int e = lane; e < 256; e += 32) {
                    int r = e >> 4, c = e & 15;
                    int tr = wm * 64 + i * 16 + r;
                    int tc = wn * 32 + j * 16 + c;
                    float v = fmaxf(stage[r * 20 + c] + ba[tc], 0.0f);
                    Af[tr * 136 + tc] = __float2half(v);
                }
                __syncwarp();
                wmma::fill_fragment(acc[i][j], 0.0f);
            }
        }
    }
    __syncthreads();   // T complete; Wbuf1 free for G2's k=1 prefetch

    // ================= GEMM 2: C = relu(T @ Wb + bb) =================
    #pragma unroll
    for (int k = 0; k < 4; k++) {
        asm volatile("cp.async.wait_group 0;\n" ::: "memory");
        __syncthreads();
        if (k < 3) prefetch_W((k + 1) & 1, (k + 1) * 32, Wbh, Wbl);

        __half* BhB = (__half*)(smem_raw + ((k & 1) ? WBUF1 : WBUF0));
        __half* BlB = BhB + 4352;

        #pragma unroll
        for (int kk = 0; kk < 32; kk += 16) {
            wmma::fragment<wmma::matrix_a, 16, 16, 16, __half, wmma::row_major> a[4];
            wmma::fragment<wmma::matrix_b, 16, 16, 16, __half, wmma::row_major> bh[2], bl[2];
            #pragma unroll
            for (int i = 0; i < 4; i++)
                wmma::load_matrix_sync(a[i], Af + (wm * 64 + i * 16) * 136 + k * 32 + kk, 136);
            #pragma unroll
            for (int j = 0; j < 2; j++) {
                wmma::load_matrix_sync(bh[j], BhB + kk * 136 + wn * 32 + j * 16, 136);
                wmma::load_matrix_sync(bl[j], BlB + kk * 136 + wn * 32 + j * 16, 136);
            }
            #pragma unroll
            for (int i = 0; i < 4; i++)
                #pragma unroll
                for (int j = 0; j < 2; j++) {
                    wmma::mma_sync(acc[i][j], a[i], bl[j], acc[i][j]);
                    wmma::mma_sync(acc[i][j], a[i], bh[j], acc[i][j]);
                }
        }
        __syncthreads();
    }

    // epilogue 2: bias + relu -> output. stage aliases Wbuf0 (last tile = buf1)
    {
        float* stage = (float*)(smem_raw + WBUF0) + warp * 320;
        #pragma unroll
        for (int i = 0; i < 4; i++) {
            #pragma unroll
            for (int j = 0; j < 2; j++) {
                wmma::store_matrix_sync(stage, acc[i][j], 20, wmma::mem_row_major);
                __syncwarp();
                #pragma unroll
                for (int e = lane; e < 256; e += 32) {
                    int r = e >> 4, c = e & 15;
                    int gr = row0 + wm * 64 + i * 16 + r;
                    int gc = wn * 32 + j * 16 + c;
                    if (gr < Nn) {
                        float v = fmaxf(stage[r * 20 + c] + bb[gc], 0.0f);
                        size_t idx = (size_t)gr * HID + gc;
                        if (Ch) Ch[idx] = __float2half(v);
                        else    Cf[idx] = v;
                    }
                }
                __syncwarp();
            }
        }
    }
}

// ---------------------------------------------------------------------------
// Fused pool + head (batch sorted -> contiguous ranges, no atomics)
// ---------------------------------------------------------------------------
__global__ __launch_bounds__(128) void pool_head_kernel(
    const float* __restrict__ h,
    const int* __restrict__ batch, int Nn,
    const float* __restrict__ Ws, const float* __restrict__ bs,
    const float* __restrict__ WlS, const float* __restrict__ blS,
    const float* __restrict__ WlP, const float* __restrict__ blP,
    const float* __restrict__ WnR, const float* __restrict__ bnR,
    float* __restrict__ out, int G)
{
    __shared__ float p[128];
    __shared__ float gv[64];
    const int g = blockIdx.x;
    const int tid = threadIdx.x;

    int lo = 0, hi = Nn;
    while (lo < hi) { int m = (lo + hi) >> 1; if (batch[m] < g) lo = m + 1; else hi = m; }
    int start = lo;
    hi = Nn;
    while (lo < hi) { int m = (lo + hi) >> 1; if (batch[m] < g + 1) lo = m + 1; else hi = m; }
    int end = lo;

    float s = 0.0f;
    for (int i = start; i < end; i++)
        s += h[(size_t)i * HID + tid];
    float inv = 1.0f / fmaxf((float)(end - start), 1.0f);
    p[tid] = s * inv;
    __syncthreads();

    if (tid < 64) {
        float acc = bs[tid];
        #pragma unroll 8
        for (int k = 0; k < 128; k++) acc += p[k] * Ws[k * 64 + tid];
        gv[tid] = fmaxf(acc, 0.0f);
    }
    __syncthreads();

    if (tid < 3) {
        const float* w = (tid == 0) ? WlS : (tid == 1) ? WlP : WnR;
        float acc = (tid == 0) ? blS[0] : (tid == 1) ? blP[0] : bnR[0];
        #pragma unroll 8
        for (int j = 0; j < 64; j++) acc += gv[j] * w[j];
        out[(size_t)tid * G + g] = acc;
    }
}

// ---------------------------------------------------------------------------
// Launch
// ---------------------------------------------------------------------------
extern "C" void kernel_launch(void* const* d_in, const int* in_sizes, int n_in,
                              void* d_out, int out_size)
{
    const float* x     = (const float*)d_in[0];
    const int*   ei    = (const int*)d_in[1];
    const int*   batch = (const int*)d_in[2];
    const float* W1a = (const float*)d_in[3];
    const float* b1a = (const float*)d_in[4];
    const float* W1b = (const float*)d_in[5];
    const float* b1b = (const float*)d_in[6];
    const float* W2a = (const float*)d_in[7];
    const float* b2a = (const float*)d_in[8];
    const float* W2b = (const float*)d_in[9];
    const float* b2b = (const float*)d_in[10];
    const float* Ws  = (const float*)d_in[11];
    const float* bs  = (const float*)d_in[12];
    const float* WlS = (const float*)d_in[13];
    const float* blS = (const float*)d_in[14];
    const float* WlP = (const float*)d_in[15];
    const float* blP = (const float*)d_in[16];
    const float* WnR = (const float*)d_in[17];
    const float* bnR = (const float*)d_in[18];
    float* out = (float*)d_out;

    const int Nn = in_sizes[0] / HID;      // 50000
    const int E  = in_sizes[1] / 2;        // 1600000
    const int G  = out_size / 3;           // 2048
    const int*   src = ei;
    const int*   dst = ei + E;

    float *h2;
    __half *xh, *hh, *Wh, *Wl;
    int *cur, *esrc;
    cudaGetSymbolAddress((void**)&xh,     g_xh);
    cudaGetSymbolAddress((void**)&hh,     g_hh);
    cudaGetSymbolAddress((void**)&h2,     g_h2);
    cudaGetSymbolAddress((void**)&cur,    g_cur);
    cudaGetSymbolAddress((void**)&esrc,   g_esrc);
    cudaGetSymbolAddress((void**)&Wh,     g_Wh);
    cudaGetSymbolAddress((void**)&Wl,     g_Wl);

    static int smem_set = 0;
    if (!smem_set) {
        cudaFuncSetAttribute(fused_layer_kernel,
                             cudaFuncAttributeMaxDynamicSharedMemorySize, FUSED_SMEM);
        smem_set = 1;
    }

    const int layer_blocks = (Nn + 127) / 128;
    const int n8 = Nn * HID / 8;
    const int WSZ = HID * HID;

    const int fill_blocks = (E + 255) / 256;
    const int f2h_blocks  = (n8 + 255) / 256;
    const int psp_blocks  = (4 * WSZ + 255) / 256;

    // ---- fused prep (fill + f2h + presplit) ----
    cudaMemsetAsync(cur, 0, Nn * sizeof(int));
    prep_kernel<<<fill_blocks + f2h_blocks + psp_blocks, 256>>>(
        src, dst, cur, esrc, E, fill_blocks,
        x, xh, n8, f2h_blocks,
        W1a, W1b, W2a, W2b, Wh, Wl);

    // ---- layer 1 (gather + MLP fused) ----
    fused_layer_kernel<<<layer_blocks, 256, FUSED_SMEM>>>(
        xh, esrc, cur,
        Wh + 0 * WSZ, Wl + 0 * WSZ, b1a, Wh + 1 * WSZ, Wl + 1 * WSZ, b1b,
        nullptr, hh, Nn);

    // ---- layer 2 (gather + MLP fused) ----
    fused_layer_kernel<<<layer_blocks, 256, FUSED_SMEM>>>(
        hh, esrc, cur,
        Wh + 2 * WSZ, Wl + 2 * WSZ, b2a, Wh + 3 * WSZ, Wl + 3 * WSZ, b2b,
        h2, nullptr, Nn);

    // ---- fused pool + head ----
    pool_head_kernel<<<G, 128>>>(h2, batch, Nn, Ws, bs, WlS, blS, WlP, blP,
                                 WnR, bnR, out, G);
}

// round 15
// speedup vs baseline: 1.6243x; 1.6243x over previous
#include <cuda_runtime.h>
#include <cuda_bf16.h>
#include <cuda_fp16.h>
#include <mma.h>
#include <cstdint>

using namespace nvcuda;

#define MAXN 50048
#define HID 128
#define MAXG 2048
#define MAXDEG 128

// Scratch (device globals; allocation is forbidden)
__device__ __half g_aggh[(size_t)MAXN * HID];
__device__ __half g_xh [(size_t)MAXN * HID];
__device__ __half g_hh [(size_t)MAXN * HID];
__device__ float  g_h2 [(size_t)MAXN * HID];
__device__ int    g_cur[MAXN];
__device__ int    g_esrc[(size_t)MAXN * MAXDEG];
__device__ __half g_Wh[4][HID * HID];
__device__ __half g_Wl[4][HID * HID];

// ---------------------------------------------------------------------------
// cp.async helpers
// ---------------------------------------------------------------------------
__device__ __forceinline__ void cp_async16(uint32_t dst, const void* src, int src_bytes)
{
    asm volatile("cp.async.ca.shared.global [%0], [%1], 16, %2;\n"
                 :: "r"(dst), "l"(src), "r"(src_bytes));
}
__device__ __forceinline__ void cp_commit()
{
    asm volatile("cp.async.commit_group;\n" ::: "memory");
}

// ---------------------------------------------------------------------------
// Fused prep kernel: edge fill + x f32->f16 + weight pre-split
// ---------------------------------------------------------------------------
__global__ __launch_bounds__(256) void prep_kernel(
    const int* __restrict__ src, const int* __restrict__ dst,
    int* __restrict__ cur, int* __restrict__ esrc, int E, int fill_blocks,
    const float* __restrict__ x, __half* __restrict__ xh, int n8, int f2h_blocks,
    const float* __restrict__ W1a, const float* __restrict__ W1b,
    const float* __restrict__ W2a, const float* __restrict__ W2b,
    __half* __restrict__ Wh, __half* __restrict__ Wl)
{
    int b = blockIdx.x;
    if (b < fill_blocks) {
        int e = b * 256 + threadIdx.x;
        if (e < E) {
            int d = dst[e];
            int pos = atomicAdd(&cur[d], 1);
            if (pos < MAXDEG) esrc[(size_t)d * MAXDEG + pos] = src[e];
        }
    } else if (b < fill_blocks + f2h_blocks) {
        int i = (b - fill_blocks) * 256 + threadIdx.x;
        if (i < n8) {
            float4 a = *reinterpret_cast<const float4*>(x + (size_t)i * 8);
            float4 c = *reinterpret_cast<const float4*>(x + (size_t)i * 8 + 4);
            uint4 u;
            *reinterpret_cast<__half2*>(&u.x) = __floats2half2_rn(a.x, a.y);
            *reinterpret_cast<__half2*>(&u.y) = __floats2half2_rn(a.z, a.w);
            *reinterpret_cast<__half2*>(&u.z) = __floats2half2_rn(c.x, c.y);
            *reinterpret_cast<__half2*>(&u.w) = __floats2half2_rn(c.z, c.w);
            *reinterpret_cast<uint4*>(xh + (size_t)i * 8) = u;
        }
    } else {
        int i = (b - fill_blocks - f2h_blocks) * 256 + threadIdx.x;
        if (i < 4 * HID * HID) {
            int plane = i >> 14, idx = i & 16383;
            const float* s = (plane == 0) ? W1a : (plane == 1) ? W1b
                           : (plane == 2) ? W2a : W2b;
            float v = s[idx];
            __half h = __float2half(v);
            __half l = __float2half(v - __half2float(h));
            Wh[i] = h;
            Wl[i] = l;
        }
    }
}

// ---------------------------------------------------------------------------
// Gather aggregation (fp16 in, fp16 out) — at the L2 cap; standalone for
// high occupancy (fusing it into the MLP regressed: R13).
// ---------------------------------------------------------------------------
__device__ __forceinline__ void acc_row(const uint4& u, float4& a, float4& b)
{
    float2 f;
    f = __half22float2(*reinterpret_cast<const __half2*>(&u.x)); a.x += f.x; a.y += f.y;
    f = __half22float2(*reinterpret_cast<const __half2*>(&u.y)); a.z += f.x; a.w += f.y;
    f = __half22float2(*reinterpret_cast<const __half2*>(&u.z)); b.x += f.x; b.y += f.y;
    f = __half22float2(*reinterpret_cast<const __half2*>(&u.w)); b.z += f.x; b.w += f.y;
}

__global__ __launch_bounds__(256) void gather_agg_h_kernel(
    const __half* __restrict__ xh, const int* __restrict__ esrc,
    const int* __restrict__ deg_arr, __half* __restrict__ out, int Nn)
{
    int node = blockIdx.x * 16 + (threadIdx.x >> 4);
    int l16  = threadIdx.x & 15;
    if (node >= Nn) return;
    int deg = min(deg_arr[node], MAXDEG);
    const int* row = esrc + (size_t)node * MAXDEG;
    const int col = l16 * 8;

    float4 accA = make_float4(0.f, 0.f, 0.f, 0.f);
    float4 accB = make_float4(0.f, 0.f, 0.f, 0.f);
    {
        uint4 u = *reinterpret_cast<const uint4*>(xh + (size_t)node * HID + col);
        acc_row(u, accA, accB);
    }
    int e = 0;
    for (; e + 4 <= deg; e += 4) {
        int4 s = *reinterpret_cast<const int4*>(row + e);
        uint4 u0 = *reinterpret_cast<const uint4*>(xh + (size_t)s.x * HID + col);
        uint4 u1 = *reinterpret_cast<const uint4*>(xh + (size_t)s.y * HID + col);
        uint4 u2 = *reinterpret_cast<const uint4*>(xh + (size_t)s.z * HID + col);
        uint4 u3 = *reinterpret_cast<const uint4*>(xh + (size_t)s.w * HID + col);
        acc_row(u0, accA, accB);
        acc_row(u1, accA, accB);
        acc_row(u2, accA, accB);
        acc_row(u3, accA, accB);
    }
    for (; e < deg; e++) {
        int s = __ldg(row + e);
        uint4 u = *reinterpret_cast<const uint4*>(xh + (size_t)s * HID + col);
        acc_row(u, accA, accB);
    }
    uint4 o;
    *reinterpret_cast<__half2*>(&o.x) = __floats2half2_rn(accA.x, accA.y);
    *reinterpret_cast<__half2*>(&o.y) = __floats2half2_rn(accA.z, accA.w);
    *reinterpret_cast<__half2*>(&o.z) = __floats2half2_rn(accB.x, accB.y);
    *reinterpret_cast<__half2*>(&o.w) = __floats2half2_rn(accB.z, accB.w);
    *reinterpret_cast<uint4*>(out + (size_t)node * HID + col) = o;
}

// ---------------------------------------------------------------------------
// Fused layer MLP (fp16, pre-split weights, cp.async double-buffered) — the
// proven R10 structure (no reg-count cap; 2 CTA/SM is the operating point).
// Dynamic smem (88 KB):
//   Ah buf0 [0,10240)  buf1 [10240,20480)
//   Bh/Bl buf0 [20480,37888) buf1 [37888,55296)
//   Th [55296, 90112)
// ---------------------------------------------------------------------------
#define A_BUF   10240
#define B_BASE  20480
#define B_BUF   17408
#define TH_OFF  55296
#define FUSED_SMEM 90112

__global__ __launch_bounds__(256) void fused_mlp_h_kernel(
    const __half* __restrict__ A,
    const __half* __restrict__ Wah, const __half* __restrict__ Wal,
    const float* __restrict__ ba,
    const __half* __restrict__ Wbh, const __half* __restrict__ Wbl,
    const float* __restrict__ bb,
    float* __restrict__ Cf, __half* __restrict__ Ch, int Nrows)
{
    extern __shared__ char smem_raw[];
    const uint32_t smem_u32 = (uint32_t)__cvta_generic_to_shared(smem_raw);
    __half* Th = (__half*)(smem_raw + TH_OFF);
    float* stagef = (float*)smem_raw;                  // alias of Ah buf0

    const int tid  = threadIdx.x;
    const int warp = tid >> 5;
    const int lane = tid & 31;
    const int wm = warp & 1;
    const int wn = warp >> 1;
    const int row0 = blockIdx.x * 128;
    float* stage = stagef + warp * 320;

    auto load_A_tile = [&](int buf, int kc) {
        uint32_t sA = smem_u32 + buf * A_BUF;
        #pragma unroll
        for (int i = tid; i < 512; i += 256) {
            int r = i >> 2, c8 = (i & 3) * 8;
            int gr = row0 + r;
            int ok = (gr < Nrows) ? 16 : 0;
            const __half* src = A + (size_t)(ok ? gr : 0) * HID + kc + c8;
            cp_async16(sA + (r * 40 + c8) * 2, src, ok);
        }
    };
    auto load_W_tile = [&](int buf, int kc, const __half* Wh_, const __half* Wl_) {
        uint32_t sBh = smem_u32 + B_BASE + buf * B_BUF;
        uint32_t sBl = sBh + 4352 * 2;
        #pragma unroll
        for (int i = tid; i < 512; i += 256) {
            int r = i >> 4, c8 = (i & 15) * 8;
            size_t goff = (size_t)(kc + r) * HID + c8;
            cp_async16(sBh + (r * 136 + c8) * 2, Wh_ + goff, 16);
            cp_async16(sBl + (r * 136 + c8) * 2, Wl_ + goff, 16);
        }
    };

    wmma::fragment<wmma::accumulator, 16, 16, 16, float> acc[4][2];
    #pragma unroll
    for (int i = 0; i < 4; i++)
        #pragma unroll
        for (int j = 0; j < 2; j++) wmma::fill_fragment(acc[i][j], 0.0f);

    // ================= GEMM 1: T = relu(A @ Wa + ba) =================
    load_A_tile(0, 0);
    load_W_tile(0, 0, Wah, Wal);
    cp_commit();

    #pragma unroll
    for (int k = 0; k < 4; k++) {
        if (k < 3) {
            load_A_tile((k + 1) & 1, (k + 1) * 32);
            load_W_tile((k + 1) & 1, (k + 1) * 32, Wah, Wal);
            cp_commit();
            asm volatile("cp.async.wait_group 1;\n" ::: "memory");
        } else {
            asm volatile("cp.async.wait_group 0;\n" ::: "memory");
        }
        __syncthreads();

        __half* AhB = (__half*)(smem_raw + (k & 1) * A_BUF);
        __half* BhB = (__half*)(smem_raw + B_BASE + (k & 1) * B_BUF);
        __half* BlB = BhB + 4352;

        #pragma unroll
        for (int kk = 0; kk < 32; kk += 16) {
            wmma::fragment<wmma::matrix_a, 16, 16, 16, __half, wmma::row_major> a[4];
            wmma::fragment<wmma::matrix_b, 16, 16, 16, __half, wmma::row_major> bh[2], bl[2];
            #pragma unroll
            for (int i = 0; i < 4; i++)
                wmma::load_matrix_sync(a[i], AhB + (wm * 64 + i * 16) * 40 + kk, 40);
            #pragma unroll
            for (int j = 0; j < 2; j++) {
                wmma::load_matrix_sync(bh[j], BhB + kk * 136 + wn * 32 + j * 16, 136);
                wmma::load_matrix_sync(bl[j], BlB + kk * 136 + wn * 32 + j * 16, 136);
            }
            #pragma unroll
            for (int i = 0; i < 4; i++)
                #pragma unroll
                for (int j = 0; j < 2; j++) {
                    wmma::mma_sync(acc[i][j], a[i], bl[j], acc[i][j]);
                    wmma::mma_sync(acc[i][j], a[i], bh[j], acc[i][j]);
                }
        }
        __syncthreads();
    }

    // Prefetch GEMM2's first W tile NOW — overlaps with epilogue 1.
    load_W_tile(0, 0, Wbh, Wbl);
    cp_commit();

    // epilogue 1: bias + relu -> Th (fp16); stage aliases Ah buf0
    #pragma unroll
    for (int i = 0; i < 4; i++) {
        #pragma unroll
        for (int j = 0; j < 2; j++) {
            wmma::store_matrix_sync(stage, acc[i][j], 20, wmma::mem_row_major);
            __syncwarp();
            #pragma unroll
            for (int e = lane; e < 256; e += 32) {
                int r = e >> 4, c = e & 15;
                int tr = wm * 64 + i * 16 + r;
                int tc = wn * 32 + j * 16 + c;
                float v = fmaxf(stage[r * 20 + c] + ba[tc], 0.0f);
                Th[tr * 136 + tc] = __float2half(v);
            }
            __syncwarp();
            wmma::fill_fragment(acc[i][j], 0.0f);
        }
    }
    __syncthreads();   // Th fully written before GEMM2 mma reads it

    // ================= GEMM 2: C = relu(T @ Wb + bb) =================
    #pragma unroll
    for (int k = 0; k < 4; k++) {
        if (k < 3) {
            load_W_tile((k + 1) & 1, (k + 1) * 32, Wbh, Wbl);
            cp_commit();
            asm volatile("cp.async.wait_group 1;\n" ::: "memory");
        } else {
            asm volatile("cp.async.wait_group 0;\n" ::: "memory");
        }
        __syncthreads();

        __half* BhB = (__half*)(smem_raw + B_BASE + (k & 1) * B_BUF);
        __half* BlB = BhB + 4352;

        #pragma unroll
        for (int kk = 0; kk < 32; kk += 16) {
            wmma::fragment<wmma::matrix_a, 16, 16, 16, __half, wmma::row_major> a[4];
            wmma::fragment<wmma::matrix_b, 16, 16, 16, __half, wmma::row_major> bh[2], bl[2];
            #pragma unroll
            for (int i = 0; i < 4; i++)
                wmma::load_matrix_sync(a[i], Th + (wm * 64 + i * 16) * 136 + k * 32 + kk, 136);
            #pragma unroll
            for (int j = 0; j < 2; j++) {
                wmma::load_matrix_sync(bh[j], BhB + kk * 136 + wn * 32 + j * 16, 136);
                wmma::load_matrix_sync(bl[j], BlB + kk * 136 + wn * 32 + j * 16, 136);
            }
            #pragma unroll
            for (int i = 0; i < 4; i++)
                #pragma unroll
                for (int j = 0; j < 2; j++) {
                    wmma::mma_sync(acc[i][j], a[i], bl[j], acc[i][j]);
                    wmma::mma_sync(acc[i][j], a[i], bh[j], acc[i][j]);
                }
        }
        __syncthreads();
    }

    // epilogue 2: bias + relu -> fp32 and/or fp16 output
    #pragma unroll
    for (int i = 0; i < 4; i++) {
        #pragma unroll
        for (int j = 0; j < 2; j++) {
            wmma::store_matrix_sync(stage, acc[i][j], 20, wmma::mem_row_major);
            __syncwarp();
            #pragma unroll
            for (int e = lane; e < 256; e += 32) {
                int r = e >> 4, c = e & 15;
                int gr = row0 + wm * 64 + i * 16 + r;
                int gc = wn * 32 + j * 16 + c;
                if (gr < Nrows) {
                    float v = fmaxf(stage[r * 20 + c] + bb[gc], 0.0f);
                    size_t idx = (size_t)gr * HID + gc;
                    if (Cf) Cf[idx] = v;
                    if (Ch) Ch[idx] = __float2half(v);
                }
            }
            __syncwarp();
        }
    }
}

// ---------------------------------------------------------------------------
// Fused pool + head — 4 independent accumulator chains so LDGs pipeline
// (R13 profile: serial s+=load chain made this 22.5us; floor is ~5us).
// ---------------------------------------------------------------------------
__global__ __launch_bounds__(128) void pool_head_kernel(
    const float* __restrict__ h,
    const int* __restrict__ batch, int Nn,
    const float* __restrict__ Ws, const float* __restrict__ bs,
    const float* __restrict__ WlS, const float* __restrict__ blS,
    const float* __restrict__ WlP, const float* __restrict__ blP,
    const float* __restrict__ WnR, const float* __restrict__ bnR,
    float* __restrict__ out, int G)
{
    __shared__ float p[128];
    __shared__ float gv[64];
    const int g = blockIdx.x;
    const int tid = threadIdx.x;

    int lo = 0, hi = Nn;
    while (lo < hi) { int m = (lo + hi) >> 1; if (batch[m] < g) lo = m + 1; else hi = m; }
    int start = lo;
    hi = Nn;
    while (lo < hi) { int m = (lo + hi) >> 1; if (batch[m] < g + 1) lo = m + 1; else hi = m; }
    int end = lo;

    float s0 = 0.f, s1 = 0.f, s2 = 0.f, s3 = 0.f;
    int i = start;
    for (; i + 4 <= end; i += 4) {
        s0 += h[(size_t)(i    ) * HID + tid];
        s1 += h[(size_t)(i + 1) * HID + tid];
        s2 += h[(size_t)(i + 2) * HID + tid];
        s3 += h[(size_t)(i + 3) * HID + tid];
    }
    for (; i < end; i++) s0 += h[(size_t)i * HID + tid];
    float s = (s0 + s1) + (s2 + s3);
    float inv = 1.0f / fmaxf((float)(end - start), 1.0f);
    p[tid] = s * inv;
    __syncthreads();

    if (tid < 64) {
        float acc = bs[tid];
        #pragma unroll 8
        for (int k = 0; k < 128; k++) acc += p[k] * Ws[k * 64 + tid];
        gv[tid] = fmaxf(acc, 0.0f);
    }
    __syncthreads();

    if (tid < 3) {
        const float* w = (tid == 0) ? WlS : (tid == 1) ? WlP : WnR;
        float acc = (tid == 0) ? blS[0] : (tid == 1) ? blP[0] : bnR[0];
        #pragma unroll 8
        for (int j = 0; j < 64; j++) acc += gv[j] * w[j];
        out[(size_t)tid * G + g] = acc;
    }
}

// ---------------------------------------------------------------------------
// Launch
// ---------------------------------------------------------------------------
extern "C" void kernel_launch(void* const* d_in, const int* in_sizes, int n_in,
                              void* d_out, int out_size)
{
    const float* x     = (const float*)d_in[0];
    const int*   ei    = (const int*)d_in[1];
    const int*   batch = (const int*)d_in[2];
    const float* W1a = (const float*)d_in[3];
    const float* b1a = (const float*)d_in[4];
    const float* W1b = (const float*)d_in[5];
    const float* b1b = (const float*)d_in[6];
    const float* W2a = (const float*)d_in[7];
    const float* b2a = (const float*)d_in[8];
    const float* W2b = (const float*)d_in[9];
    const float* b2b = (const float*)d_in[10];
    const float* Ws  = (const float*)d_in[11];
    const float* bs  = (const float*)d_in[12];
    const float* WlS = (const float*)d_in[13];
    const float* blS = (const float*)d_in[14];
    const float* WlP = (const float*)d_in[15];
    const float* blP = (const float*)d_in[16];
    const float* WnR = (const float*)d_in[17];
    const float* bnR = (const float*)d_in[18];
    float* out = (float*)d_out;

    const int Nn = in_sizes[0] / HID;      // 50000
    const int E  = in_sizes[1] / 2;        // 1600000
    const int G  = out_size / 3;           // 2048
    const int*   src = ei;
    const int*   dst = ei + E;

    float *h2;
    __half *aggh, *xh, *hh, *Wh, *Wl;
    int *cur, *esrc;
    cudaGetSymbolAddress((void**)&aggh,   g_aggh);
    cudaGetSymbolAddress((void**)&xh,     g_xh);
    cudaGetSymbolAddress((void**)&hh,     g_hh);
    cudaGetSymbolAddress((void**)&h2,     g_h2);
    cudaGetSymbolAddress((void**)&cur,    g_cur);
    cudaGetSymbolAddress((void**)&esrc,   g_esrc);
    cudaGetSymbolAddress((void**)&Wh,     g_Wh);
    cudaGetSymbolAddress((void**)&Wl,     g_Wl);

    static int smem_set = 0;
    if (!smem_set) {
        cudaFuncSetAttribute(fused_mlp_h_kernel,
                             cudaFuncAttributeMaxDynamicSharedMemorySize, FUSED_SMEM);
        smem_set = 1;
    }

    const int gemm_blocks = (Nn + 127) / 128;
    const int agg_blocks  = (Nn + 15) / 16;
    const int n8 = Nn * HID / 8;
    const int WSZ = HID * HID;

    const int fill_blocks = (E + 255) / 256;
    const int f2h_blocks  = (n8 + 255) / 256;
    const int psp_blocks  = (4 * WSZ + 255) / 256;

    // ---- fused prep (fill + f2h + presplit) ----
    cudaMemsetAsync(cur, 0, Nn * sizeof(int));
    prep_kernel<<<fill_blocks + f2h_blocks + psp_blocks, 256>>>(
        src, dst, cur, esrc, E, fill_blocks,
        x, xh, n8, f2h_blocks,
        W1a, W1b, W2a, W2b, Wh, Wl);

    // ---- layer 1 ----
    gather_agg_h_kernel<<<agg_blocks, 256>>>(xh, esrc, cur, aggh, Nn);
    fused_mlp_h_kernel<<<gemm_blocks, 256, FUSED_SMEM>>>(
        aggh, Wh + 0 * WSZ, Wl + 0 * WSZ, b1a, Wh + 1 * WSZ, Wl + 1 * WSZ, b1b,
        nullptr, hh, Nn);

    // ---- layer 2 ----
    gather_agg_h_kernel<<<agg_blocks, 256>>>(hh, esrc, cur, aggh, Nn);
    fused_mlp_h_kernel<<<gemm_blocks, 256, FUSED_SMEM>>>(
        aggh, Wh + 2 * WSZ, Wl + 2 * WSZ, b2a, Wh + 3 * WSZ, Wl + 3 * WSZ, b2b,
        h2, nullptr, Nn);

    // ---- fused pool + head ----
    pool_head_kernel<<<G, 128>>>(h2, batch, Nn, Ws, bs, WlS, blS, WlP, blP,
                                 WnR, bnR, out, G);
}

// round 17
// speedup vs baseline: 1.6488x; 1.0151x over previous
#include <cuda_runtime.h>
#include <cuda_bf16.h>
#include <cuda_fp16.h>
#include <mma.h>
#include <cstdint>

using namespace nvcuda;

#define MAXN 50048
#define HID 128
#define MAXG 2048
#define MAXDEG 128

// Scratch (device globals; allocation is forbidden)
__device__ __half g_aggh[(size_t)MAXN * HID];
__device__ __half g_xh [(size_t)MAXN * HID];
__device__ __half g_hh [(size_t)MAXN * HID];
__device__ float  g_h2 [(size_t)MAXN * HID];
__device__ int    g_cur[MAXN];
__device__ int    g_esrc[(size_t)MAXN * MAXDEG];
__device__ __half g_Wh[4][HID * HID];
__device__ __half g_Wl[4][HID * HID];

// ---------------------------------------------------------------------------
// cp.async helpers
// ---------------------------------------------------------------------------
__device__ __forceinline__ void cp_async16(uint32_t dst, const void* src, int src_bytes)
{
    asm volatile("cp.async.ca.shared.global [%0], [%1], 16, %2;\n"
                 :: "r"(dst), "l"(src), "r"(src_bytes));
}
__device__ __forceinline__ void cp_commit()
{
    asm volatile("cp.async.commit_group;\n" ::: "memory");
}

// ---------------------------------------------------------------------------
// Fused prep kernel: edge fill + x f32->f16 + weight pre-split (hi+lo)
// ---------------------------------------------------------------------------
__global__ __launch_bounds__(256) void prep_kernel(
    const int* __restrict__ src, const int* __restrict__ dst,
    int* __restrict__ cur, int* __restrict__ esrc, int E, int fill_blocks,
    const float* __restrict__ x, __half* __restrict__ xh, int n8, int f2h_blocks,
    const float* __restrict__ W1a, const float* __restrict__ W1b,
    const float* __restrict__ W2a, const float* __restrict__ W2b,
    __half* __restrict__ Wh, __half* __restrict__ Wl)
{
    int b = blockIdx.x;
    if (b < fill_blocks) {
        int e = b * 256 + threadIdx.x;
        if (e < E) {
            int d = dst[e];
            int pos = atomicAdd(&cur[d], 1);
            if (pos < MAXDEG) esrc[(size_t)d * MAXDEG + pos] = src[e];
        }
    } else if (b < fill_blocks + f2h_blocks) {
        int i = (b - fill_blocks) * 256 + threadIdx.x;
        if (i < n8) {
            float4 a = *reinterpret_cast<const float4*>(x + (size_t)i * 8);
            float4 c = *reinterpret_cast<const float4*>(x + (size_t)i * 8 + 4);
            uint4 u;
            *reinterpret_cast<__half2*>(&u.x) = __floats2half2_rn(a.x, a.y);
            *reinterpret_cast<__half2*>(&u.y) = __floats2half2_rn(a.z, a.w);
            *reinterpret_cast<__half2*>(&u.z) = __floats2half2_rn(c.x, c.y);
            *reinterpret_cast<__half2*>(&u.w) = __floats2half2_rn(c.z, c.w);
            *reinterpret_cast<uint4*>(xh + (size_t)i * 8) = u;
        }
    } else {
        int i = (b - fill_blocks - f2h_blocks) * 256 + threadIdx.x;
        if (i < 4 * HID * HID) {
            int plane = i >> 14, idx = i & 16383;
            const float* s = (plane == 0) ? W1a : (plane == 1) ? W1b
                           : (plane == 2) ? W2a : W2b;
            float v = s[idx];
            __half h = __float2half(v);
            __half l = __float2half(v - __half2float(h));
            Wh[i] = h;
            Wl[i] = l;
        }
    }
}

// ---------------------------------------------------------------------------
// Gather aggregation (fp16 in, fp16 out).
// Pairwise fp16 HADD2 then fp32 accumulate: 20 fma-pipe ops / 2 edges vs 32.
// ---------------------------------------------------------------------------
__device__ __forceinline__ void acc_row(const uint4& u, float4& a, float4& b)
{
    float2 f;
    f = __half22float2(*reinterpret_cast<const __half2*>(&u.x)); a.x += f.x; a.y += f.y;
    f = __half22float2(*reinterpret_cast<const __half2*>(&u.y)); a.z += f.x; a.w += f.y;
    f = __half22float2(*reinterpret_cast<const __half2*>(&u.z)); b.x += f.x; b.y += f.y;
    f = __half22float2(*reinterpret_cast<const __half2*>(&u.w)); b.z += f.x; b.w += f.y;
}

__device__ __forceinline__ void acc_pair(const uint4& u0, const uint4& u1,
                                         float4& a, float4& b)
{
    __half2 s;
    float2 f;
    s = __hadd2(*reinterpret_cast<const __half2*>(&u0.x),
                *reinterpret_cast<const __half2*>(&u1.x));
    f = __half22float2(s); a.x += f.x; a.y += f.y;
    s = __hadd2(*reinterpret_cast<const __half2*>(&u0.y),
                *reinterpret_cast<const __half2*>(&u1.y));
    f = __half22float2(s); a.z += f.x; a.w += f.y;
    s = __hadd2(*reinterpret_cast<const __half2*>(&u0.z),
                *reinterpret_cast<const __half2*>(&u1.z));
    f = __half22float2(s); b.x += f.x; b.y += f.y;
    s = __hadd2(*reinterpret_cast<const __half2*>(&u0.w),
                *reinterpret_cast<const __half2*>(&u1.w));
    f = __half22float2(s); b.z += f.x; b.w += f.y;
}

__global__ __launch_bounds__(256) void gather_agg_h_kernel(
    const __half* __restrict__ xh, const int* __restrict__ esrc,
    const int* __restrict__ deg_arr, __half* __restrict__ out, int Nn)
{
    int node = blockIdx.x * 16 + (threadIdx.x >> 4);
    int l16  = threadIdx.x & 15;
    if (node >= Nn) return;
    int deg = min(deg_arr[node], MAXDEG);
    const int* row = esrc + (size_t)node * MAXDEG;
    const int col = l16 * 8;

    float4 accA = make_float4(0.f, 0.f, 0.f, 0.f);
    float4 accB = make_float4(0.f, 0.f, 0.f, 0.f);
    {
        uint4 u = *reinterpret_cast<const uint4*>(xh + (size_t)node * HID + col);
        acc_row(u, accA, accB);
    }
    int e = 0;
    for (; e + 4 <= deg; e += 4) {
        int4 s = *reinterpret_cast<const int4*>(row + e);
        uint4 u0 = *reinterpret_cast<const uint4*>(xh + (size_t)s.x * HID + col);
        uint4 u1 = *reinterpret_cast<const uint4*>(xh + (size_t)s.y * HID + col);
        uint4 u2 = *reinterpret_cast<const uint4*>(xh + (size_t)s.z * HID + col);
        uint4 u3 = *reinterpret_cast<const uint4*>(xh + (size_t)s.w * HID + col);
        acc_pair(u0, u1, accA, accB);
        acc_pair(u2, u3, accA, accB);
    }
    for (; e < deg; e++) {
        int s = __ldg(row + e);
        uint4 u = *reinterpret_cast<const uint4*>(xh + (size_t)s * HID + col);
        acc_row(u, accA, accB);
    }
    uint4 o;
    *reinterpret_cast<__half2*>(&o.x) = __floats2half2_rn(accA.x, accA.y);
    *reinterpret_cast<__half2*>(&o.y) = __floats2half2_rn(accA.z, accA.w);
    *reinterpret_cast<__half2*>(&o.z) = __floats2half2_rn(accB.x, accB.y);
    *reinterpret_cast<__half2*>(&o.w) = __floats2half2_rn(accB.z, accB.w);
    *reinterpret_cast<uint4*>(out + (size_t)node * HID + col) = o;
}

// ---------------------------------------------------------------------------
// Fused layer MLP (fp16 A, fp16 hi+lo W, cp.async double-buffered) — the
// proven R10/R15 structure (no reg caps, no gather fusion: both falsified).
// Dynamic smem (88 KB):
//   Ah buf0 [0,10240)  buf1 [10240,20480)
//   Bh/Bl buf0 [20480,37888) buf1 [37888,55296)
//   Th [55296, 90112)
// ---------------------------------------------------------------------------
#define A_BUF   10240
#define B_BASE  20480
#define B_BUF   17408
#define TH_OFF  55296
#define FUSED_SMEM 90112

__global__ __launch_bounds__(256) void fused_mlp_h_kernel(
    const __half* __restrict__ A,
    const __half* __restrict__ Wah, const __half* __restrict__ Wal,
    const float* __restrict__ ba,
    const __half* __restrict__ Wbh, const __half* __restrict__ Wbl,
    const float* __restrict__ bb,
    float* __restrict__ Cf, __half* __restrict__ Ch, int Nrows)
{
    extern __shared__ char smem_raw[];
    const uint32_t smem_u32 = (uint32_t)__cvta_generic_to_shared(smem_raw);
    __half* Th = (__half*)(smem_raw + TH_OFF);
    float* stagef = (float*)smem_raw;                  // alias of Ah buf0

    const int tid  = threadIdx.x;
    const int warp = tid >> 5;
    const int lane = tid & 31;
    const int wm = warp & 1;
    const int wn = warp >> 1;
    const int row0 = blockIdx.x * 128;
    float* stage = stagef + warp * 320;

    auto load_A_tile = [&](int buf, int kc) {
        uint32_t sA = smem_u32 + buf * A_BUF;
        #pragma unroll
        for (int i = tid; i < 512; i += 256) {
            int r = i >> 2, c8 = (i & 3) * 8;
            int gr = row0 + r;
            int ok = (gr < Nrows) ? 16 : 0;
            const __half* src = A + (size_t)(ok ? gr : 0) * HID + kc + c8;
            cp_async16(sA + (r * 40 + c8) * 2, src, ok);
        }
    };
    auto load_W_tile = [&](int buf, int kc, const __half* Wh_, const __half* Wl_) {
        uint32_t sBh = smem_u32 + B_BASE + buf * B_BUF;
        uint32_t sBl = sBh + 4352 * 2;
        #pragma unroll
        for (int i = tid; i < 512; i += 256) {
            int r = i >> 4, c8 = (i & 15) * 8;
            size_t goff = (size_t)(kc + r) * HID + c8;
            cp_async16(sBh + (r * 136 + c8) * 2, Wh_ + goff, 16);
            cp_async16(sBl + (r * 136 + c8) * 2, Wl_ + goff, 16);
        }
    };

    wmma::fragment<wmma::accumulator, 16, 16, 16, float> acc[4][2];
    #pragma unroll
    for (int i = 0; i < 4; i++)
        #pragma unroll
        for (int j = 0; j < 2; j++) wmma::fill_fragment(acc[i][j], 0.0f);

    // ================= GEMM 1: T = relu(A @ Wa + ba) =================
    load_A_tile(0, 0);
    load_W_tile(0, 0, Wah, Wal);
    cp_commit();

    #pragma unroll
    for (int k = 0; k < 4; k++) {
        if (k < 3) {
            load_A_tile((k + 1) & 1, (k + 1) * 32);
            load_W_tile((k + 1) & 1, (k + 1) * 32, Wah, Wal);
            cp_commit();
            asm volatile("cp.async.wait_group 1;\n" ::: "memory");
        } else {
            asm volatile("cp.async.wait_group 0;\n" ::: "memory");
        }
        __syncthreads();

        __half* AhB = (__half*)(smem_raw + (k & 1) * A_BUF);
        __half* BhB = (__half*)(smem_raw + B_BASE + (k & 1) * B_BUF);
        __half* BlB = BhB + 4352;

        #pragma unroll
        for (int kk = 0; kk < 32; kk += 16) {
            wmma::fragment<wmma::matrix_a, 16, 16, 16, __half, wmma::row_major> a[4];
            wmma::fragment<wmma::matrix_b, 16, 16, 16, __half, wmma::row_major> bh[2], bl[2];
            #pragma unroll
            for (int i = 0; i < 4; i++)
                wmma::load_matrix_sync(a[i], AhB + (wm * 64 + i * 16) * 40 + kk, 40);
            #pragma unroll
            for (int j = 0; j < 2; j++) {
                wmma::load_matrix_sync(bh[j], BhB + kk * 136 + wn * 32 + j * 16, 136);
                wmma::load_matrix_sync(bl[j], BlB + kk * 136 + wn * 32 + j * 16, 136);
            }
            #pragma unroll
            for (int i = 0; i < 4; i++)
                #pragma unroll
                for (int j = 0; j < 2; j++) {
                    wmma::mma_sync(acc[i][j], a[i], bl[j], acc[i][j]);
                    wmma::mma_sync(acc[i][j], a[i], bh[j], acc[i][j]);
                }
        }
        __syncthreads();
    }

    // Prefetch GEMM2's first W tile NOW — overlaps with epilogue 1.
    load_W_tile(0, 0, Wbh, Wbl);
    cp_commit();

    // epilogue 1: bias + relu -> Th (fp16); stage aliases Ah buf0
    #pragma unroll
    for (int i = 0; i < 4; i++) {
        #pragma unroll
        for (int j = 0; j < 2; j++) {
            wmma::store_matrix_sync(stage, acc[i][j], 20, wmma::mem_row_major);
            __syncwarp();
            #pragma unroll
            for (int e = lane; e < 256; e += 32) {
                int r = e >> 4, c = e & 15;
                int tr = wm * 64 + i * 16 + r;
                int tc = wn * 32 + j * 16 + c;
                float v = fmaxf(stage[r * 20 + c] + ba[tc], 0.0f);
                Th[tr * 136 + tc] = __float2half(v);
            }
            __syncwarp();
            wmma::fill_fragment(acc[i][j], 0.0f);
        }
    }
    __syncthreads();   // Th fully written before GEMM2 mma reads it

    // ================= GEMM 2: C = relu(T @ Wb + bb) =================
    #pragma unroll
    for (int k = 0; k < 4; k++) {
        if (k < 3) {
            load_W_tile((k + 1) & 1, (k + 1) * 32, Wbh, Wbl);
            cp_commit();
            asm volatile("cp.async.wait_group 1;\n" ::: "memory");
        } else {
            asm volatile("cp.async.wait_group 0;\n" ::: "memory");
        }
        __syncthreads();

        __half* BhB = (__half*)(smem_raw + B_BASE + (k & 1) * B_BUF);
        __half* BlB = BhB + 4352;

        #pragma unroll
        for (int kk = 0; kk < 32; kk += 16) {
            wmma::fragment<wmma::matrix_a, 16, 16, 16, __half, wmma::row_major> a[4];
            wmma::fragment<wmma::matrix_b, 16, 16, 16, __half, wmma::row_major> bh[2], bl[2];
            #pragma unroll
            for (int i = 0; i < 4; i++)
                wmma::load_matrix_sync(a[i], Th + (wm * 64 + i * 16) * 136 + k * 32 + kk, 136);
            #pragma unroll
            for (int j = 0; j < 2; j++) {
                wmma::load_matrix_sync(bh[j], BhB + kk * 136 + wn * 32 + j * 16, 136);
                wmma::load_matrix_sync(bl[j], BlB + kk * 136 + wn * 32 + j * 16, 136);
            }
            #pragma unroll
            for (int i = 0; i < 4; i++)
                #pragma unroll
                for (int j = 0; j < 2; j++) {
                    wmma::mma_sync(acc[i][j], a[i], bl[j], acc[i][j]);
                    wmma::mma_sync(acc[i][j], a[i], bh[j], acc[i][j]);
                }
        }
        __syncthreads();
    }

    // epilogue 2: bias + relu -> fp32 and/or fp16 output
    #pragma unroll
    for (int i = 0; i < 4; i++) {
        #pragma unroll
        for (int j = 0; j < 2; j++) {
            wmma::store_matrix_sync(stage, acc[i][j], 20, wmma::mem_row_major);
            __syncwarp();
            #pragma unroll
            for (int e = lane; e < 256; e += 32) {
                int r = e >> 4, c = e & 15;
                int gr = row0 + wm * 64 + i * 16 + r;
                int gc = wn * 32 + j * 16 + c;
                if (gr < Nrows) {
                    float v = fmaxf(stage[r * 20 + c] + bb[gc], 0.0f);
                    size_t idx = (size_t)gr * HID + gc;
                    if (Cf) Cf[idx] = v;
                    if (Ch) Ch[idx] = __float2half(v);
                }
            }
            __syncwarp();
        }
    }
}

// ---------------------------------------------------------------------------
// Fused pool + head — 4 independent accumulator chains (LDGs pipeline)
// ---------------------------------------------------------------------------
__global__ __launch_bounds__(128) void pool_head_kernel(
    const float* __restrict__ h,
    const int* __restrict__ batch, int Nn,
    const float* __restrict__ Ws, const float* __restrict__ bs,
    const float* __restrict__ WlS, const float* __restrict__ blS,
    const float* __restrict__ WlP, const float* __restrict__ blP,
    const float* __restrict__ WnR, const float* __restrict__ bnR,
    float* __restrict__ out, int G)
{
    __shared__ float p[128];
    __shared__ float gv[64];
    const int g = blockIdx.x;
    const int tid = threadIdx.x;

    int lo = 0, hi = Nn;
    while (lo < hi) { int m = (lo + hi) >> 1; if (batch[m] < g) lo = m + 1; else hi = m; }
    int start = lo;
    hi = Nn;
    while (lo < hi) { int m = (lo + hi) >> 1; if (batch[m] < g + 1) lo = m + 1; else hi = m; }
    int end = lo;

    float s0 = 0.f, s1 = 0.f, s2 = 0.f, s3 = 0.f;
    int i = start;
    for (; i + 4 <= end; i += 4) {
        s0 += h[(size_t)(i    ) * HID + tid];
        s1 += h[(size_t)(i + 1) * HID + tid];
        s2 += h[(size_t)(i + 2) * HID + tid];
        s3 += h[(size_t)(i + 3) * HID + tid];
    }
    for (; i < end; i++) s0 += h[(size_t)i * HID + tid];
    float s = (s0 + s1) + (s2 + s3);
    float inv = 1.0f / fmaxf((float)(end - start), 1.0f);
    p[tid] = s * inv;
    __syncthreads();

    if (tid < 64) {
        float acc = bs[tid];
        #pragma unroll 8
        for (int k = 0; k < 128; k++) acc += p[k] * Ws[k * 64 + tid];
        gv[tid] = fmaxf(acc, 0.0f);
    }
    __syncthreads();

    if (tid < 3) {
        const float* w = (tid == 0) ? WlS : (tid == 1) ? WlP : WnR;
        float acc = (tid == 0) ? blS[0] : (tid == 1) ? blP[0] : bnR[0];
        #pragma unroll 8
        for (int j = 0; j < 64; j++) acc += gv[j] * w[j];
        out[(size_t)tid * G + g] = acc;
    }
}

// ---------------------------------------------------------------------------
// Launch
// ---------------------------------------------------------------------------
extern "C" void kernel_launch(void* const* d_in, const int* in_sizes, int n_in,
                              void* d_out, int out_size)
{
    const float* x     = (const float*)d_in[0];
    const int*   ei    = (const int*)d_in[1];
    const int*   batch = (const int*)d_in[2];
    const float* W1a = (const float*)d_in[3];
    const float* b1a = (const float*)d_in[4];
    const float* W1b = (const float*)d_in[5];
    const float* b1b = (const float*)d_in[6];
    const float* W2a = (const float*)d_in[7];
    const float* b2a = (const float*)d_in[8];
    const float* W2b = (const float*)d_in[9];
    const float* b2b = (const float*)d_in[10];
    const float* Ws  = (const float*)d_in[11];
    const float* bs  = (const float*)d_in[12];
    const float* WlS = (const float*)d_in[13];
    const float* blS = (const float*)d_in[14];
    const float* WlP = (const float*)d_in[15];
    const float* blP = (const float*)d_in[16];
    const float* WnR = (const float*)d_in[17];
    const float* bnR = (const float*)d_in[18];
    float* out = (float*)d_out;

    const int Nn = in_sizes[0] / HID;      // 50000
    const int E  = in_sizes[1] / 2;        // 1600000
    const int G  = out_size / 3;           // 2048
    const int*   src = ei;
    const int*   dst = ei + E;

    float *h2;
    __half *aggh, *xh, *hh, *Wh, *Wl;
    int *cur, *esrc;
    cudaGetSymbolAddress((void**)&aggh,   g_aggh);
    cudaGetSymbolAddress((void**)&xh,     g_xh);
    cudaGetSymbolAddress((void**)&hh,     g_hh);
    cudaGetSymbolAddress((void**)&h2,     g_h2);
    cudaGetSymbolAddress((void**)&cur,    g_cur);
    cudaGetSymbolAddress((void**)&esrc,   g_esrc);
    cudaGetSymbolAddress((void**)&Wh,     g_Wh);
    cudaGetSymbolAddress((void**)&Wl,     g_Wl);

    static int smem_set = 0;
    if (!smem_set) {
        cudaFuncSetAttribute(fused_mlp_h_kernel,
                             cudaFuncAttributeMaxDynamicSharedMemorySize, FUSED_SMEM);
        smem_set = 1;
    }

    const int gemm_blocks = (Nn + 127) / 128;
    const int agg_blocks  = (Nn + 15) / 16;
    const int n8 = Nn * HID / 8;
    const int WSZ = HID * HID;

    const int fill_blocks = (E + 255) / 256;
    const int f2h_blocks  = (n8 + 255) / 256;
    const int psp_blocks  = (4 * WSZ + 255) / 256;

    // ---- fused prep (fill + f2h + presplit) ----
    cudaMemsetAsync(cur, 0, Nn * sizeof(int));
    prep_kernel<<<fill_blocks + f2h_blocks + psp_blocks, 256>>>(
        src, dst, cur, esrc, E, fill_blocks,
        x, xh, n8, f2h_blocks,
        W1a, W1b, W2a, W2b, Wh, Wl);

    // ---- layer 1 ----
    gather_agg_h_kernel<<<agg_blocks, 256>>>(xh, esrc, cur, aggh, Nn);
    fused_mlp_h_kernel<<<gemm_blocks, 256, FUSED_SMEM>>>(
        aggh, Wh + 0 * WSZ, Wl + 0 * WSZ, b1a, Wh + 1 * WSZ, Wl + 1 * WSZ, b1b,
        nullptr, hh, Nn);

    // ---- layer 2 ----
    gather_agg_h_kernel<<<agg_blocks, 256>>>(hh, esrc, cur, aggh, Nn);
    fused_mlp_h_kernel<<<gemm_blocks, 256, FUSED_SMEM>>>(
        aggh, Wh + 2 * WSZ, Wl + 2 * WSZ, b2a, Wh + 3 * WSZ, Wl + 3 * WSZ, b2b,
        h2, nullptr, Nn);

    // ---- fused pool + head ----
    pool_head_kernel<<<G, 128>>>(h2, batch, Nn, Ws, bs, WlS, blS, WlP, blP,
                                 WnR, bnR, out, G);
}